// round 1
// baseline (speedup 1.0000x reference)
#include <cuda_runtime.h>
#include <cuda_bf16.h>
#include <math.h>

// Problem dims
#define BB 32
#define TT 128
#define EE 512
#define HH 1024
#define LDIM 256
#define LL 5000
#define TB 4096          // T*B
#define G4 4096          // 4*H

// ---------------- device scratch (no allocs allowed) ----------------
__device__ float  g_xg_enc[(size_t)G4 * TB];   // [n][r] pre-gates encoder (64MB)
__device__ float  g_xg_dec[(size_t)G4 * TB];   // [n][r] pre-gates decoder (64MB)
__device__ float  g_hsT[(size_t)HH * TB];      // decoder hidden states, [k][r] (16MB)
__device__ float4 g_h[2][HH / 4 * BB];         // ping-pong h, [k4][b] as float4
__device__ float  g_c[HH * BB];                // c, [j][b]

__device__ __forceinline__ float sigmoidf_(float x) { return 1.f / (1.f + expf(-x)); }

// ---------------- zero initial state ----------------
__global__ void zero_state_kernel() {
    int i = blockIdx.x * blockDim.x + threadIdx.x;
    if (i < HH * BB) {
        ((float*)g_h)[i] = 0.f;   // zeroes g_h[0]
        g_c[i] = 0.f;
    }
}

// ---------------- pre-gates GEMM: XgT[n][r] = sum_k W[n][k]*emb[sel(r)][k] + b1[n]+b2[n]
// MODE 0: encoder (sel(r) = sentence_flat[r]), KDIM=512
// MODE 1: decoder (sel(r): t=r>>5,b=r&31; t==0 -> 1 else label_seq[b*128+t-1]), KDIM=256
#define BM 128
#define BN 128
#define BKK 16

template <int KDIM, int MODE>
__global__ __launch_bounds__(256) void pregates_kernel(
    const float* __restrict__ W, const float* __restrict__ emb,
    const int* __restrict__ idx, const float* __restrict__ b1,
    const float* __restrict__ b2)
{
    __shared__ float As[BKK][BM + 4];
    __shared__ float Bs[BKK][BN + 4];
    float* xgT = (MODE == 0) ? g_xg_enc : g_xg_dec;

    int tid = threadIdx.x;
    int tx = tid & 15, ty = tid >> 4;
    int mBase = blockIdx.y * BM;
    int rBase = blockIdx.x * BN;

    int rowsel[2];
#pragma unroll
    for (int it = 0; it < 2; it++) {
        int i4 = tid + it * 256;
        int r = i4 >> 2;
        int rg = rBase + r;
        if (MODE == 0) {
            rowsel[it] = idx[rg];
        } else {
            int tt = rg >> 5, bbi = rg & 31;
            rowsel[it] = (tt == 0) ? 1 : idx[bbi * TT + tt - 1];
        }
    }

    float acc[8][8];
#pragma unroll
    for (int i = 0; i < 8; i++)
#pragma unroll
        for (int j = 0; j < 8; j++) acc[i][j] = 0.f;

    for (int kt = 0; kt < KDIM / BKK; kt++) {
#pragma unroll
        for (int it = 0; it < 2; it++) {
            int i4 = tid + it * 256;
            int m = i4 >> 2, k4 = i4 & 3;
            float4 v = *reinterpret_cast<const float4*>(
                &W[(size_t)(mBase + m) * KDIM + kt * BKK + k4 * 4]);
            As[k4 * 4 + 0][m] = v.x; As[k4 * 4 + 1][m] = v.y;
            As[k4 * 4 + 2][m] = v.z; As[k4 * 4 + 3][m] = v.w;
        }
#pragma unroll
        for (int it = 0; it < 2; it++) {
            int i4 = tid + it * 256;
            int r = i4 >> 2, k4 = i4 & 3;
            float4 v = *reinterpret_cast<const float4*>(
                &emb[(size_t)rowsel[it] * KDIM + kt * BKK + k4 * 4]);
            Bs[k4 * 4 + 0][r] = v.x; Bs[k4 * 4 + 1][r] = v.y;
            Bs[k4 * 4 + 2][r] = v.z; Bs[k4 * 4 + 3][r] = v.w;
        }
        __syncthreads();
#pragma unroll
        for (int k = 0; k < BKK; k++) {
            float a[8], bv[8];
            *(float4*)&a[0] = *(const float4*)&As[k][ty * 8];
            *(float4*)&a[4] = *(const float4*)&As[k][ty * 8 + 4];
            *(float4*)&bv[0] = *(const float4*)&Bs[k][tx * 8];
            *(float4*)&bv[4] = *(const float4*)&Bs[k][tx * 8 + 4];
#pragma unroll
            for (int i = 0; i < 8; i++)
#pragma unroll
                for (int j = 0; j < 8; j++) acc[i][j] += a[i] * bv[j];
        }
        __syncthreads();
    }

#pragma unroll
    for (int i = 0; i < 8; i++) {
        int n = mBase + ty * 8 + i;
        float bias = b1[n] + b2[n];
        float4 o0 = make_float4(acc[i][0] + bias, acc[i][1] + bias,
                                acc[i][2] + bias, acc[i][3] + bias);
        float4 o1 = make_float4(acc[i][4] + bias, acc[i][5] + bias,
                                acc[i][6] + bias, acc[i][7] + bias);
        *(float4*)&xgT[(size_t)n * TB + rBase + tx * 8] = o0;
        *(float4*)&xgT[(size_t)n * TB + rBase + tx * 8 + 4] = o1;
    }
}

// ---------------- one LSTM step (recurrent GEMM + elementwise), fused ----------------
// grid 256 CTAs x 256 threads. CTA covers 4 j values. 8 warps = (2 j-pairs) x (4 K-splits).
// lane = batch. h stored as float4 [k4][b]; c as [j][b]; Xg as [n][r=t*32+b].
__global__ __launch_bounds__(256) void lstm_step_kernel(
    const float* __restrict__ Whh, int t, int parity, int is_dec)
{
    __shared__ float red[4][4][4][32];  // [jlocal][gate][ksplit][b]
    int tid = threadIdx.x;
    int lane = tid & 31;
    int w = tid >> 5;
    int jp = w & 1;        // which j-pair
    int ks = w >> 1;       // K split 0..3
    int jbase = blockIdx.x * 4;

    const float4* __restrict__ h_in = g_h[parity];
    float* __restrict__ h_out = (float*)g_h[parity ^ 1];
    const float4* __restrict__ W4 = reinterpret_cast<const float4*>(Whh);
    const float* __restrict__ xgT = is_dec ? g_xg_dec : g_xg_enc;

    float acc[2][4];
#pragma unroll
    for (int jx = 0; jx < 2; jx++)
#pragma unroll
        for (int g = 0; g < 4; g++) acc[jx][g] = 0.f;

    int j0 = jbase + jp * 2;
    int k4beg = ks * 64;
#pragma unroll 2
    for (int k4 = k4beg; k4 < k4beg + 64; k4++) {
        float4 hv = h_in[k4 * 32 + lane];
#pragma unroll
        for (int jx = 0; jx < 2; jx++) {
            int j = j0 + jx;
#pragma unroll
            for (int g = 0; g < 4; g++) {
                float4 wv = W4[(size_t)(g * HH + j) * (HH / 4) + k4];
                acc[jx][g] += wv.x * hv.x + wv.y * hv.y + wv.z * hv.z + wv.w * hv.w;
            }
        }
    }

#pragma unroll
    for (int jx = 0; jx < 2; jx++)
#pragma unroll
        for (int g = 0; g < 4; g++) red[jp * 2 + jx][g][ks][lane] = acc[jx][g];
    __syncthreads();

    if (w < 4) {
        int j = jbase + w;
        float s[4];
#pragma unroll
        for (int g = 0; g < 4; g++) {
            s[g] = red[w][g][0][lane] + red[w][g][1][lane] +
                   red[w][g][2][lane] + red[w][g][3][lane] +
                   xgT[(size_t)(g * HH + j) * TB + t * 32 + lane];
        }
        float ig = sigmoidf_(s[0]);
        float fg = sigmoidf_(s[1]);
        float gg = tanhf(s[2]);
        float og = sigmoidf_(s[3]);
        int ci = j * 32 + lane;
        float c = fg * g_c[ci] + ig * gg;
        g_c[ci] = c;
        float h = og * tanhf(c);
        h_out[(((j >> 2) * 32 + lane) << 2) + (j & 3)] = h;
        if (is_dec) g_hsT[(size_t)j * TB + t * 32 + lane] = h;
    }
}

// ---------------- projection: out[r][l] = sum_k hsT[k][r]*Ws[l][k] + b[l] ----------------
__global__ __launch_bounds__(256) void proj_kernel(
    float* __restrict__ out, const float* __restrict__ Ws,
    const float* __restrict__ bsc)
{
    __shared__ float As[BKK][BM + 4];
    __shared__ float Bs[BKK][BN + 4];
    int tid = threadIdx.x;
    int tx = tid & 15, ty = tid >> 4;
    int rBase = blockIdx.y * BM;
    int lBase = blockIdx.x * BN;

    float acc[8][8];
#pragma unroll
    for (int i = 0; i < 8; i++)
#pragma unroll
        for (int j = 0; j < 8; j++) acc[i][j] = 0.f;

    for (int kt = 0; kt < HH / BKK; kt++) {
#pragma unroll
        for (int it = 0; it < 2; it++) {
            int i4 = tid + it * 256;
            int k = i4 >> 5, r4 = i4 & 31;
            float4 v = *reinterpret_cast<const float4*>(
                &g_hsT[(size_t)(kt * BKK + k) * TB + rBase + r4 * 4]);
            *(float4*)&As[k][r4 * 4] = v;
        }
#pragma unroll
        for (int it = 0; it < 2; it++) {
            int i4 = tid + it * 256;
            int l = i4 >> 2, k4 = i4 & 3;
            int lg = lBase + l;
            float4 v = make_float4(0.f, 0.f, 0.f, 0.f);
            if (lg < LL)
                v = *reinterpret_cast<const float4*>(
                    &Ws[(size_t)lg * HH + kt * BKK + k4 * 4]);
            Bs[k4 * 4 + 0][l] = v.x; Bs[k4 * 4 + 1][l] = v.y;
            Bs[k4 * 4 + 2][l] = v.z; Bs[k4 * 4 + 3][l] = v.w;
        }
        __syncthreads();
#pragma unroll
        for (int k = 0; k < BKK; k++) {
            float a[8], bv[8];
            *(float4*)&a[0] = *(const float4*)&As[k][ty * 8];
            *(float4*)&a[4] = *(const float4*)&As[k][ty * 8 + 4];
            *(float4*)&bv[0] = *(const float4*)&Bs[k][tx * 8];
            *(float4*)&bv[4] = *(const float4*)&Bs[k][tx * 8 + 4];
#pragma unroll
            for (int i = 0; i < 8; i++)
#pragma unroll
                for (int j = 0; j < 8; j++) acc[i][j] += a[i] * bv[j];
        }
        __syncthreads();
    }

#pragma unroll
    for (int i = 0; i < 8; i++) {
        int r = rBase + ty * 8 + i;
#pragma unroll
        for (int jv = 0; jv < 2; jv++) {
            int l0 = lBase + tx * 8 + jv * 4;
            if (l0 + 3 < LL) {
                float4 o = make_float4(acc[i][jv * 4 + 0] + bsc[l0 + 0],
                                       acc[i][jv * 4 + 1] + bsc[l0 + 1],
                                       acc[i][jv * 4 + 2] + bsc[l0 + 2],
                                       acc[i][jv * 4 + 3] + bsc[l0 + 3]);
                *(float4*)&out[(size_t)r * LL + l0] = o;
            } else {
#pragma unroll
                for (int c = 0; c < 4; c++) {
                    int l = l0 + c;
                    if (l < LL) out[(size_t)r * LL + l] = acc[i][jv * 4 + c] + bsc[l];
                }
            }
        }
    }
}

// ---------------- host launcher ----------------
extern "C" void kernel_launch(void* const* d_in, const int* in_sizes, int n_in,
                              void* d_out, int out_size)
{
    const int*   sentence  = (const int*)d_in[0];
    const int*   label_seq = (const int*)d_in[1];
    const float* word_emb  = (const float*)d_in[2];
    const float* label_emb = (const float*)d_in[3];
    const float* enc_W_ih  = (const float*)d_in[4];
    const float* enc_W_hh  = (const float*)d_in[5];
    const float* enc_b_ih  = (const float*)d_in[6];
    const float* enc_b_hh  = (const float*)d_in[7];
    const float* dec_W_ih  = (const float*)d_in[8];
    const float* dec_W_hh  = (const float*)d_in[9];
    const float* dec_b_ih  = (const float*)d_in[10];
    const float* dec_b_hh  = (const float*)d_in[11];
    const float* W_score   = (const float*)d_in[12];
    const float* b_score   = (const float*)d_in[13];
    float* out = (float*)d_out;

    zero_state_kernel<<<32, 1024>>>();

    dim3 gg(TB / BN, G4 / BM);
    pregates_kernel<EE, 0><<<gg, 256>>>(enc_W_ih, word_emb, sentence, enc_b_ih, enc_b_hh);
    pregates_kernel<LDIM, 1><<<gg, 256>>>(dec_W_ih, label_emb, label_seq, dec_b_ih, dec_b_hh);

    for (int t = 0; t < TT; t++)
        lstm_step_kernel<<<256, 256>>>(enc_W_hh, t, t & 1, 0);
    for (int t = 0; t < TT; t++)
        lstm_step_kernel<<<256, 256>>>(dec_W_hh, t, t & 1, 1);

    proj_kernel<<<dim3((LL + BN - 1) / BN, TB / BM), 256>>>(out, W_score, b_score);
}

// round 2
// speedup vs baseline: 1.8080x; 1.8080x over previous
#include <cuda_runtime.h>
#include <cuda_bf16.h>
#include <math.h>

// Problem dims
#define BB 32
#define TT 128
#define EE 512
#define HH 1024
#define LDIM 256
#define LL 5000
#define TB 4096          // T*B
#define G4 4096          // 4*H

// ---------------- device scratch (no allocs allowed) ----------------
__device__ float  g_xg_enc[(size_t)G4 * TB];   // [n][r] pre-gates encoder (64MB)
__device__ float  g_xg_dec[(size_t)G4 * TB];   // [n][r] pre-gates decoder (64MB)
__device__ float  g_hsT[(size_t)HH * TB];      // decoder hidden states, [k][r] (16MB)
__device__ float4 g_h[2][HH / 4 * BB];         // ping-pong h, [k4][b] as float4
__device__ float  g_c[HH * BB];                // c, [j][b]

__device__ __forceinline__ float sigmoidf_(float x) { return 1.f / (1.f + expf(-x)); }

// ---- packed f32x2 helpers (sm_103a FFMA2) ----
__device__ __forceinline__ void ffma2(unsigned long long& d,
                                      unsigned long long a,
                                      unsigned long long b) {
    asm("fma.rn.f32x2 %0, %1, %2, %0;" : "+l"(d) : "l"(a), "l"(b));
}
__device__ __forceinline__ unsigned long long pack2(float x, float y) {
    unsigned long long r;
    asm("mov.b64 %0, {%1, %2};" : "=l"(r) : "f"(x), "f"(y));
    return r;
}
__device__ __forceinline__ float2 unpack2(unsigned long long v) {
    unsigned a, b;
    asm("mov.b64 {%0, %1}, %2;" : "=r"(a), "=r"(b) : "l"(v));
    return make_float2(__uint_as_float(a), __uint_as_float(b));
}

// ---------------- zero initial state ----------------
__global__ void zero_state_kernel() {
    int i = blockIdx.x * blockDim.x + threadIdx.x;
    if (i < HH * BB) {
        ((float*)g_h)[i] = 0.f;   // zeroes g_h[0]
        g_c[i] = 0.f;
    }
}

// ---------------- pre-gates GEMM: XgT[n][r] = sum_k W[n][k]*emb[sel(r)][k] + b1[n]+b2[n]
#define BM 128
#define BN 128
#define BKK 16

template <int KDIM, int MODE>
__global__ __launch_bounds__(256) void pregates_kernel(
    const float* __restrict__ W, const float* __restrict__ emb,
    const int* __restrict__ idx, const float* __restrict__ b1,
    const float* __restrict__ b2)
{
    __shared__ float As[BKK][BM + 4];
    __shared__ float Bs[BKK][BN + 4];
    float* xgT = (MODE == 0) ? g_xg_enc : g_xg_dec;

    int tid = threadIdx.x;
    int tx = tid & 15, ty = tid >> 4;
    int mBase = blockIdx.y * BM;
    int rBase = blockIdx.x * BN;

    int rowsel[2];
#pragma unroll
    for (int it = 0; it < 2; it++) {
        int i4 = tid + it * 256;
        int r = i4 >> 2;
        int rg = rBase + r;
        if (MODE == 0) {
            rowsel[it] = idx[rg];
        } else {
            int tt = rg >> 5, bbi = rg & 31;
            rowsel[it] = (tt == 0) ? 1 : idx[bbi * TT + tt - 1];
        }
    }

    unsigned long long acc2[8][4];
#pragma unroll
    for (int i = 0; i < 8; i++)
#pragma unroll
        for (int q = 0; q < 4; q++) acc2[i][q] = 0ull;

    for (int kt = 0; kt < KDIM / BKK; kt++) {
#pragma unroll
        for (int it = 0; it < 2; it++) {
            int i4 = tid + it * 256;
            int m = i4 >> 2, k4 = i4 & 3;
            float4 v = *reinterpret_cast<const float4*>(
                &W[(size_t)(mBase + m) * KDIM + kt * BKK + k4 * 4]);
            As[k4 * 4 + 0][m] = v.x; As[k4 * 4 + 1][m] = v.y;
            As[k4 * 4 + 2][m] = v.z; As[k4 * 4 + 3][m] = v.w;
        }
#pragma unroll
        for (int it = 0; it < 2; it++) {
            int i4 = tid + it * 256;
            int r = i4 >> 2, k4 = i4 & 3;
            float4 v = *reinterpret_cast<const float4*>(
                &emb[(size_t)rowsel[it] * KDIM + kt * BKK + k4 * 4]);
            Bs[k4 * 4 + 0][r] = v.x; Bs[k4 * 4 + 1][r] = v.y;
            Bs[k4 * 4 + 2][r] = v.z; Bs[k4 * 4 + 3][r] = v.w;
        }
        __syncthreads();
#pragma unroll
        for (int k = 0; k < BKK; k++) {
            float a[8];
            *(float4*)&a[0] = *(const float4*)&As[k][ty * 8];
            *(float4*)&a[4] = *(const float4*)&As[k][ty * 8 + 4];
            unsigned long long bq[4];
#pragma unroll
            for (int q = 0; q < 4; q++)
                bq[q] = *(const unsigned long long*)&Bs[k][tx * 8 + q * 2];
#pragma unroll
            for (int i = 0; i < 8; i++) {
                unsigned long long ap = pack2(a[i], a[i]);
#pragma unroll
                for (int q = 0; q < 4; q++) ffma2(acc2[i][q], ap, bq[q]);
            }
        }
        __syncthreads();
    }

#pragma unroll
    for (int i = 0; i < 8; i++) {
        int n = mBase + ty * 8 + i;
        float bias = b1[n] + b2[n];
        float2 p0 = unpack2(acc2[i][0]);
        float2 p1 = unpack2(acc2[i][1]);
        float2 p2 = unpack2(acc2[i][2]);
        float2 p3 = unpack2(acc2[i][3]);
        float4 o0 = make_float4(p0.x + bias, p0.y + bias, p1.x + bias, p1.y + bias);
        float4 o1 = make_float4(p2.x + bias, p2.y + bias, p3.x + bias, p3.y + bias);
        *(float4*)&xgT[(size_t)n * TB + rBase + tx * 8] = o0;
        *(float4*)&xgT[(size_t)n * TB + rBase + tx * 8 + 4] = o1;
    }
}

// ---------------- one LSTM step, smem-staged weights + f32x2 FMA ----------------
// grid 256 CTAs x 512 threads. CTA covers 4 j (16 weight rows). 16 warps = 16 K-splits
// of 16 k4 each. lane = batch. Weights staged coalesced into smem (64KB), compute
// reads broadcast LDS.128. h as float4 [k4][b]. Dynamic smem: 64KB Wt + 32KB red.
__global__ __launch_bounds__(512, 2) void lstm_step_kernel(
    const float* __restrict__ Whh, int t, int parity, int is_dec)
{
    extern __shared__ float smem[];
    float4* Wt = (float4*)smem;            // [16 rows][256 k4]
    float* red = smem + 16 * 1024;         // [16 rows][16 ksplit][32 lane]

    int tid = threadIdx.x;
    int lane = tid & 31;
    int w = tid >> 5;                      // ksplit 0..15
    int jbase = blockIdx.x * 4;

    const ulonglong2* __restrict__ h_in = (const ulonglong2*)g_h[parity];
    float* __restrict__ h_out = (float*)g_h[parity ^ 1];
    const float4* __restrict__ W4 = reinterpret_cast<const float4*>(Whh);
    const float* __restrict__ xgT = is_dec ? g_xg_dec : g_xg_enc;

    // stage 16 rows (r: g = r&3, jx = r>>2) coalesced
#pragma unroll
    for (int it = 0; it < 8; it++) {
        int idx = tid + it * 512;          // 0..4095
        int r = idx >> 8, k4 = idx & 255;
        int g = r & 3, jx = r >> 2;
        Wt[r * 256 + k4] = W4[(size_t)(g * HH + jbase + jx) * 256 + k4];
    }
    __syncthreads();

    unsigned long long acc[16];
#pragma unroll
    for (int r = 0; r < 16; r++) acc[r] = 0ull;

    int k4beg = w * 16;
#pragma unroll 4
    for (int kk = 0; kk < 16; kk++) {
        int k4 = k4beg + kk;
        ulonglong2 hv = h_in[k4 * 32 + lane];
#pragma unroll
        for (int r = 0; r < 16; r++) {
            ulonglong2 wv = *reinterpret_cast<const ulonglong2*>(&Wt[r * 256 + k4]);
            ffma2(acc[r], wv.x, hv.x);
            ffma2(acc[r], wv.y, hv.y);
        }
    }

#pragma unroll
    for (int r = 0; r < 16; r++) {
        float2 p = unpack2(acc[r]);
        red[(r * 16 + w) * 32 + lane] = p.x + p.y;
    }
    __syncthreads();

    if (w < 4) {
        int jx = w;
        int j = jbase + jx;
        float s[4];
#pragma unroll
        for (int g = 0; g < 4; g++) {
            int r = jx * 4 + g;
            float v = xgT[(size_t)(g * HH + j) * TB + t * 32 + lane];
#pragma unroll
            for (int ks = 0; ks < 16; ks++) v += red[(r * 16 + ks) * 32 + lane];
            s[g] = v;
        }
        float ig = sigmoidf_(s[0]);
        float fg = sigmoidf_(s[1]);
        float gg = tanhf(s[2]);
        float og = sigmoidf_(s[3]);
        int ci = j * 32 + lane;
        float c = fg * g_c[ci] + ig * gg;
        g_c[ci] = c;
        float h = og * tanhf(c);
        h_out[(((j >> 2) * 32 + lane) << 2) + (j & 3)] = h;
        if (is_dec) g_hsT[(size_t)j * TB + t * 32 + lane] = h;
    }
}

#define STEP_SMEM (16 * 1024 * 4 + 16 * 16 * 32 * 4)   // 64KB + 32KB

// ---------------- projection: out[r][l] = sum_k hsT[k][r]*Ws[l][k] + b[l] ----------------
__global__ __launch_bounds__(256) void proj_kernel(
    float* __restrict__ out, const float* __restrict__ Ws,
    const float* __restrict__ bsc)
{
    __shared__ float As[BKK][BM + 4];
    __shared__ float Bs[BKK][BN + 4];
    int tid = threadIdx.x;
    int tx = tid & 15, ty = tid >> 4;
    int rBase = blockIdx.y * BM;
    int lBase = blockIdx.x * BN;

    unsigned long long acc2[8][4];
#pragma unroll
    for (int i = 0; i < 8; i++)
#pragma unroll
        for (int q = 0; q < 4; q++) acc2[i][q] = 0ull;

    for (int kt = 0; kt < HH / BKK; kt++) {
#pragma unroll
        for (int it = 0; it < 2; it++) {
            int i4 = tid + it * 256;
            int k = i4 >> 5, r4 = i4 & 31;
            float4 v = *reinterpret_cast<const float4*>(
                &g_hsT[(size_t)(kt * BKK + k) * TB + rBase + r4 * 4]);
            *(float4*)&As[k][r4 * 4] = v;
        }
#pragma unroll
        for (int it = 0; it < 2; it++) {
            int i4 = tid + it * 256;
            int l = i4 >> 2, k4 = i4 & 3;
            int lg = lBase + l;
            float4 v = make_float4(0.f, 0.f, 0.f, 0.f);
            if (lg < LL)
                v = *reinterpret_cast<const float4*>(
                    &Ws[(size_t)lg * HH + kt * BKK + k4 * 4]);
            Bs[k4 * 4 + 0][l] = v.x; Bs[k4 * 4 + 1][l] = v.y;
            Bs[k4 * 4 + 2][l] = v.z; Bs[k4 * 4 + 3][l] = v.w;
        }
        __syncthreads();
#pragma unroll
        for (int k = 0; k < BKK; k++) {
            float a[8];
            *(float4*)&a[0] = *(const float4*)&As[k][ty * 8];
            *(float4*)&a[4] = *(const float4*)&As[k][ty * 8 + 4];
            unsigned long long bq[4];
#pragma unroll
            for (int q = 0; q < 4; q++)
                bq[q] = *(const unsigned long long*)&Bs[k][tx * 8 + q * 2];
#pragma unroll
            for (int i = 0; i < 8; i++) {
                unsigned long long ap = pack2(a[i], a[i]);
#pragma unroll
                for (int q = 0; q < 4; q++) ffma2(acc2[i][q], ap, bq[q]);
            }
        }
        __syncthreads();
    }

#pragma unroll
    for (int i = 0; i < 8; i++) {
        int r = rBase + ty * 8 + i;
        float av[8];
        float2 p0 = unpack2(acc2[i][0]);
        float2 p1 = unpack2(acc2[i][1]);
        float2 p2 = unpack2(acc2[i][2]);
        float2 p3 = unpack2(acc2[i][3]);
        av[0] = p0.x; av[1] = p0.y; av[2] = p1.x; av[3] = p1.y;
        av[4] = p2.x; av[5] = p2.y; av[6] = p3.x; av[7] = p3.y;
#pragma unroll
        for (int jv = 0; jv < 2; jv++) {
            int l0 = lBase + tx * 8 + jv * 4;
            if (l0 + 3 < LL) {
                float4 o = make_float4(av[jv * 4 + 0] + bsc[l0 + 0],
                                       av[jv * 4 + 1] + bsc[l0 + 1],
                                       av[jv * 4 + 2] + bsc[l0 + 2],
                                       av[jv * 4 + 3] + bsc[l0 + 3]);
                *(float4*)&out[(size_t)r * LL + l0] = o;
            } else {
#pragma unroll
                for (int c = 0; c < 4; c++) {
                    int l = l0 + c;
                    if (l < LL) out[(size_t)r * LL + l] = av[jv * 4 + c] + bsc[l];
                }
            }
        }
    }
}

// ---------------- host launcher ----------------
extern "C" void kernel_launch(void* const* d_in, const int* in_sizes, int n_in,
                              void* d_out, int out_size)
{
    const int*   sentence  = (const int*)d_in[0];
    const int*   label_seq = (const int*)d_in[1];
    const float* word_emb  = (const float*)d_in[2];
    const float* label_emb = (const float*)d_in[3];
    const float* enc_W_ih  = (const float*)d_in[4];
    const float* enc_W_hh  = (const float*)d_in[5];
    const float* enc_b_ih  = (const float*)d_in[6];
    const float* enc_b_hh  = (const float*)d_in[7];
    const float* dec_W_ih  = (const float*)d_in[8];
    const float* dec_W_hh  = (const float*)d_in[9];
    const float* dec_b_ih  = (const float*)d_in[10];
    const float* dec_b_hh  = (const float*)d_in[11];
    const float* W_score   = (const float*)d_in[12];
    const float* b_score   = (const float*)d_in[13];
    float* out = (float*)d_out;

    cudaFuncSetAttribute(lstm_step_kernel,
                         cudaFuncAttributeMaxDynamicSharedMemorySize, STEP_SMEM);

    zero_state_kernel<<<32, 1024>>>();

    dim3 gg(TB / BN, G4 / BM);
    pregates_kernel<EE, 0><<<gg, 256>>>(enc_W_ih, word_emb, sentence, enc_b_ih, enc_b_hh);
    pregates_kernel<LDIM, 1><<<gg, 256>>>(dec_W_ih, label_emb, label_seq, dec_b_ih, dec_b_hh);

    for (int t = 0; t < TT; t++)
        lstm_step_kernel<<<256, 512, STEP_SMEM>>>(enc_W_hh, t, t & 1, 0);
    for (int t = 0; t < TT; t++)
        lstm_step_kernel<<<256, 512, STEP_SMEM>>>(dec_W_hh, t, t & 1, 1);

    proj_kernel<<<dim3((LL + BN - 1) / BN, TB / BM), 256>>>(out, W_score, b_score);
}

// round 3
// speedup vs baseline: 2.0211x; 1.1179x over previous
#include <cuda_runtime.h>
#include <cuda_bf16.h>
#include <math.h>

// Problem dims
#define BB 32
#define TT 128
#define EE 512
#define HH 1024
#define LDIM 256
#define LL 5000
#define TB 4096          // T*B
#define G4 4096          // 4*H

#define GRID_P 128
#define NTHR_P 1024

// ---------------- device scratch (no allocs allowed) ----------------
__device__ float  g_xg_enc[(size_t)G4 * TB];   // [n][r] pre-gates encoder (64MB)
__device__ float  g_xg_dec[(size_t)G4 * TB];   // [n][r] pre-gates decoder (64MB)
__device__ float  g_hsT[(size_t)HH * TB];      // decoder hidden states, [k][r] (16MB)
__device__ float4 g_h[2][HH / 4 * BB];         // ping-pong h, [k4][b] as float4
__device__ unsigned g_bar;                     // grid barrier counter

__device__ __forceinline__ float sigmoidf_(float x) { return 1.f / (1.f + expf(-x)); }

// ---- packed f32x2 helpers (sm_103a FFMA2) ----
__device__ __forceinline__ void ffma2(unsigned long long& d,
                                      unsigned long long a,
                                      unsigned long long b) {
    asm("fma.rn.f32x2 %0, %1, %2, %0;" : "+l"(d) : "l"(a), "l"(b));
}
__device__ __forceinline__ unsigned long long pack2(float x, float y) {
    unsigned long long r;
    asm("mov.b64 %0, {%1, %2};" : "=l"(r) : "f"(x), "f"(y));
    return r;
}
__device__ __forceinline__ float2 unpack2(unsigned long long v) {
    unsigned a, b;
    asm("mov.b64 {%0, %1}, %2;" : "=r"(a), "=r"(b) : "l"(v));
    return make_float2(__uint_as_float(a), __uint_as_float(b));
}

// ---------------- zero initial state + barrier ----------------
__global__ void zero_state_kernel() {
    int i = blockIdx.x * blockDim.x + threadIdx.x;
    if (i < HH * BB) ((float*)g_h)[i] = 0.f;   // zeroes g_h[0]
    if (i == 0) g_bar = 0u;
}

// ---------------- pre-gates GEMM ----------------
#define BM 128
#define BN 128
#define BKK 16

template <int KDIM, int MODE>
__global__ __launch_bounds__(256) void pregates_kernel(
    const float* __restrict__ W, const float* __restrict__ emb,
    const int* __restrict__ idx, const float* __restrict__ b1,
    const float* __restrict__ b2)
{
    __shared__ float As[BKK][BM + 4];
    __shared__ float Bs[BKK][BN + 4];
    float* xgT = (MODE == 0) ? g_xg_enc : g_xg_dec;

    int tid = threadIdx.x;
    int tx = tid & 15, ty = tid >> 4;
    int mBase = blockIdx.y * BM;
    int rBase = blockIdx.x * BN;

    int rowsel[2];
#pragma unroll
    for (int it = 0; it < 2; it++) {
        int i4 = tid + it * 256;
        int r = i4 >> 2;
        int rg = rBase + r;
        if (MODE == 0) {
            rowsel[it] = idx[rg];
        } else {
            int tt = rg >> 5, bbi = rg & 31;
            rowsel[it] = (tt == 0) ? 1 : idx[bbi * TT + tt - 1];
        }
    }

    unsigned long long acc2[8][4];
#pragma unroll
    for (int i = 0; i < 8; i++)
#pragma unroll
        for (int q = 0; q < 4; q++) acc2[i][q] = 0ull;

    for (int kt = 0; kt < KDIM / BKK; kt++) {
#pragma unroll
        for (int it = 0; it < 2; it++) {
            int i4 = tid + it * 256;
            int m = i4 >> 2, k4 = i4 & 3;
            float4 v = *reinterpret_cast<const float4*>(
                &W[(size_t)(mBase + m) * KDIM + kt * BKK + k4 * 4]);
            As[k4 * 4 + 0][m] = v.x; As[k4 * 4 + 1][m] = v.y;
            As[k4 * 4 + 2][m] = v.z; As[k4 * 4 + 3][m] = v.w;
        }
#pragma unroll
        for (int it = 0; it < 2; it++) {
            int i4 = tid + it * 256;
            int r = i4 >> 2, k4 = i4 & 3;
            float4 v = *reinterpret_cast<const float4*>(
                &emb[(size_t)rowsel[it] * KDIM + kt * BKK + k4 * 4]);
            Bs[k4 * 4 + 0][r] = v.x; Bs[k4 * 4 + 1][r] = v.y;
            Bs[k4 * 4 + 2][r] = v.z; Bs[k4 * 4 + 3][r] = v.w;
        }
        __syncthreads();
#pragma unroll
        for (int k = 0; k < BKK; k++) {
            float a[8];
            *(float4*)&a[0] = *(const float4*)&As[k][ty * 8];
            *(float4*)&a[4] = *(const float4*)&As[k][ty * 8 + 4];
            unsigned long long bq[4];
#pragma unroll
            for (int q = 0; q < 4; q++)
                bq[q] = *(const unsigned long long*)&Bs[k][tx * 8 + q * 2];
#pragma unroll
            for (int i = 0; i < 8; i++) {
                unsigned long long ap = pack2(a[i], a[i]);
#pragma unroll
                for (int q = 0; q < 4; q++) ffma2(acc2[i][q], ap, bq[q]);
            }
        }
        __syncthreads();
    }

#pragma unroll
    for (int i = 0; i < 8; i++) {
        int n = mBase + ty * 8 + i;
        float bias = b1[n] + b2[n];
        float2 p0 = unpack2(acc2[i][0]);
        float2 p1 = unpack2(acc2[i][1]);
        float2 p2 = unpack2(acc2[i][2]);
        float2 p3 = unpack2(acc2[i][3]);
        float4 o0 = make_float4(p0.x + bias, p0.y + bias, p1.x + bias, p1.y + bias);
        float4 o1 = make_float4(p2.x + bias, p2.y + bias, p3.x + bias, p3.y + bias);
        *(float4*)&xgT[(size_t)n * TB + rBase + tx * 8] = o0;
        *(float4*)&xgT[(size_t)n * TB + rBase + tx * 8 + 4] = o1;
    }
}

// ---------------- persistent LSTM recurrence (enc 128 steps + dec 128 steps) ----
// 128 CTAs x 1024 threads, 1 CTA/SM. CTA owns 8 hidden units (32 weight rows),
// W_hh rows staged in smem ONCE per phase. c in smem. h ping-pongs via L2.
// Grid-wide sync via monotonic atomic counter (all CTAs co-resident).
// smem: Wt 32*256 float4 (128KB) + red 32*16*32 f (64KB) + c 8*32 f (1KB)
#define SMEM_PERS (32 * 256 * 16 + 32 * 16 * 32 * 4 + 8 * 32 * 4)

__global__ __launch_bounds__(NTHR_P, 1) void lstm_persistent_kernel(
    const float* __restrict__ encW, const float* __restrict__ decW)
{
    extern __shared__ float sm[];
    float4* Wt = (float4*)sm;                    // [32][256]
    float* red = sm + 32 * 1024;                 // [32][16][32]
    float* c_s = red + 32 * 16 * 32;             // [8][32]

    int tid = threadIdx.x, lane = tid & 31, w = tid >> 5;
    int ks = w >> 1, half = w & 1;
    int jbase = blockIdx.x * 8;
    int rbase = half * 16;

    // stage encoder weights
    {
        const float4* W4 = (const float4*)encW;
#pragma unroll
        for (int it = 0; it < 8; it++) {
            int idx = tid + it * NTHR_P;
            int r = idx >> 8, k4 = idx & 255;
            int g = r & 3, jx = r >> 2;
            Wt[r * 256 + k4] = W4[(size_t)(g * HH + jbase + jx) * 256 + k4];
        }
    }
    if (tid < 256) c_s[tid] = 0.f;
    __syncthreads();

    for (int s = 0; s < 256; s++) {
        if (s == 128) {
            const float4* W4 = (const float4*)decW;
#pragma unroll
            for (int it = 0; it < 8; it++) {
                int idx = tid + it * NTHR_P;
                int r = idx >> 8, k4 = idx & 255;
                int g = r & 3, jx = r >> 2;
                Wt[r * 256 + k4] = W4[(size_t)(g * HH + jbase + jx) * 256 + k4];
            }
            __syncthreads();
        }
        int t = s & 127;
        const ulonglong2* __restrict__ h_in = (const ulonglong2*)g_h[s & 1];
        float* __restrict__ h_out = (float*)g_h[(s & 1) ^ 1];
        const float* __restrict__ xgT = (s < 128) ? g_xg_enc : g_xg_dec;

        unsigned long long acc[16];
#pragma unroll
        for (int r = 0; r < 16; r++) acc[r] = 0ull;

#pragma unroll 4
        for (int kk = 0; kk < 16; kk++) {
            int k4 = ks * 16 + kk;
            ulonglong2 hv = h_in[k4 * 32 + lane];
#pragma unroll
            for (int r = 0; r < 16; r++) {
                ulonglong2 wv =
                    *reinterpret_cast<const ulonglong2*>(&Wt[(rbase + r) * 256 + k4]);
                ffma2(acc[r], wv.x, hv.x);
                ffma2(acc[r], wv.y, hv.y);
            }
        }
#pragma unroll
        for (int r = 0; r < 16; r++) {
            float2 p = unpack2(acc[r]);
            red[((rbase + r) * 16 + ks) * 32 + lane] = p.x + p.y;
        }
        __syncthreads();

        if (w < 8) {
            int jx = w, j = jbase + jx;
            float sg[4];
#pragma unroll
            for (int g = 0; g < 4; g++) {
                int r = (jx << 2) | g;
                float v = xgT[(size_t)(g * HH + j) * TB + t * 32 + lane];
#pragma unroll
                for (int k = 0; k < 16; k++) v += red[(r * 16 + k) * 32 + lane];
                sg[g] = v;
            }
            float ig = sigmoidf_(sg[0]);
            float fg = sigmoidf_(sg[1]);
            float gg = tanhf(sg[2]);
            float og = sigmoidf_(sg[3]);
            float c = fg * c_s[jx * 32 + lane] + ig * gg;
            c_s[jx * 32 + lane] = c;
            float h = og * tanhf(c);
            h_out[(((j >> 2) * 32 + lane) << 2) + (j & 3)] = h;
            if (s >= 128) g_hsT[(size_t)j * TB + t * 32 + lane] = h;
        }
        __syncthreads();

        if (tid == 0) {
            __threadfence();
            atomicAdd(&g_bar, 1u);
            unsigned target = (unsigned)(s + 1) * GRID_P;
            unsigned v;
            do {
                asm volatile("ld.acquire.gpu.global.u32 %0, [%1];"
                             : "=r"(v) : "l"(&g_bar) : "memory");
            } while (v < target);
        }
        __syncthreads();
    }
}

// ---------------- projection: out[r][l] = sum_k hsT[k][r]*Ws[l][k] + b[l] ----------------
__global__ __launch_bounds__(256) void proj_kernel(
    float* __restrict__ out, const float* __restrict__ Ws,
    const float* __restrict__ bsc)
{
    __shared__ float As[BKK][BM + 4];
    __shared__ float Bs[BKK][BN + 4];
    int tid = threadIdx.x;
    int tx = tid & 15, ty = tid >> 4;
    int rBase = blockIdx.y * BM;
    int lBase = blockIdx.x * BN;

    unsigned long long acc2[8][4];
#pragma unroll
    for (int i = 0; i < 8; i++)
#pragma unroll
        for (int q = 0; q < 4; q++) acc2[i][q] = 0ull;

    for (int kt = 0; kt < HH / BKK; kt++) {
#pragma unroll
        for (int it = 0; it < 2; it++) {
            int i4 = tid + it * 256;
            int k = i4 >> 5, r4 = i4 & 31;
            float4 v = *reinterpret_cast<const float4*>(
                &g_hsT[(size_t)(kt * BKK + k) * TB + rBase + r4 * 4]);
            *(float4*)&As[k][r4 * 4] = v;
        }
#pragma unroll
        for (int it = 0; it < 2; it++) {
            int i4 = tid + it * 256;
            int l = i4 >> 2, k4 = i4 & 3;
            int lg = lBase + l;
            float4 v = make_float4(0.f, 0.f, 0.f, 0.f);
            if (lg < LL)
                v = *reinterpret_cast<const float4*>(
                    &Ws[(size_t)lg * HH + kt * BKK + k4 * 4]);
            Bs[k4 * 4 + 0][l] = v.x; Bs[k4 * 4 + 1][l] = v.y;
            Bs[k4 * 4 + 2][l] = v.z; Bs[k4 * 4 + 3][l] = v.w;
        }
        __syncthreads();
#pragma unroll
        for (int k = 0; k < BKK; k++) {
            float a[8];
            *(float4*)&a[0] = *(const float4*)&As[k][ty * 8];
            *(float4*)&a[4] = *(const float4*)&As[k][ty * 8 + 4];
            unsigned long long bq[4];
#pragma unroll
            for (int q = 0; q < 4; q++)
                bq[q] = *(const unsigned long long*)&Bs[k][tx * 8 + q * 2];
#pragma unroll
            for (int i = 0; i < 8; i++) {
                unsigned long long ap = pack2(a[i], a[i]);
#pragma unroll
                for (int q = 0; q < 4; q++) ffma2(acc2[i][q], ap, bq[q]);
            }
        }
        __syncthreads();
    }

#pragma unroll
    for (int i = 0; i < 8; i++) {
        int r = rBase + ty * 8 + i;
        float av[8];
        float2 p0 = unpack2(acc2[i][0]);
        float2 p1 = unpack2(acc2[i][1]);
        float2 p2 = unpack2(acc2[i][2]);
        float2 p3 = unpack2(acc2[i][3]);
        av[0] = p0.x; av[1] = p0.y; av[2] = p1.x; av[3] = p1.y;
        av[4] = p2.x; av[5] = p2.y; av[6] = p3.x; av[7] = p3.y;
#pragma unroll
        for (int jv = 0; jv < 2; jv++) {
            int l0 = lBase + tx * 8 + jv * 4;
            if (l0 + 3 < LL) {
                float4 o = make_float4(av[jv * 4 + 0] + bsc[l0 + 0],
                                       av[jv * 4 + 1] + bsc[l0 + 1],
                                       av[jv * 4 + 2] + bsc[l0 + 2],
                                       av[jv * 4 + 3] + bsc[l0 + 3]);
                *(float4*)&out[(size_t)r * LL + l0] = o;
            } else {
#pragma unroll
                for (int c = 0; c < 4; c++) {
                    int l = l0 + c;
                    if (l < LL) out[(size_t)r * LL + l] = av[jv * 4 + c] + bsc[l];
                }
            }
        }
    }
}

// ---------------- host launcher ----------------
extern "C" void kernel_launch(void* const* d_in, const int* in_sizes, int n_in,
                              void* d_out, int out_size)
{
    const int*   sentence  = (const int*)d_in[0];
    const int*   label_seq = (const int*)d_in[1];
    const float* word_emb  = (const float*)d_in[2];
    const float* label_emb = (const float*)d_in[3];
    const float* enc_W_ih  = (const float*)d_in[4];
    const float* enc_W_hh  = (const float*)d_in[5];
    const float* enc_b_ih  = (const float*)d_in[6];
    const float* enc_b_hh  = (const float*)d_in[7];
    const float* dec_W_ih  = (const float*)d_in[8];
    const float* dec_W_hh  = (const float*)d_in[9];
    const float* dec_b_ih  = (const float*)d_in[10];
    const float* dec_b_hh  = (const float*)d_in[11];
    const float* W_score   = (const float*)d_in[12];
    const float* b_score   = (const float*)d_in[13];
    float* out = (float*)d_out;

    static int smem_set = 0;
    if (!smem_set) {
        cudaFuncSetAttribute(lstm_persistent_kernel,
                             cudaFuncAttributeMaxDynamicSharedMemorySize, SMEM_PERS);
        smem_set = 1;
    }

    zero_state_kernel<<<32, 1024>>>();

    dim3 gg(TB / BN, G4 / BM);
    pregates_kernel<EE, 0><<<gg, 256>>>(enc_W_ih, word_emb, sentence, enc_b_ih, enc_b_hh);
    pregates_kernel<LDIM, 1><<<gg, 256>>>(dec_W_ih, label_emb, label_seq, dec_b_ih, dec_b_hh);

    lstm_persistent_kernel<<<GRID_P, NTHR_P, SMEM_PERS>>>(enc_W_hh, dec_W_hh);

    proj_kernel<<<dim3((LL + BN - 1) / BN, TB / BM), 256>>>(out, W_score, b_score);
}